// round 13
// baseline (speedup 1.0000x reference)
#include <cuda_runtime.h>
#include <cuda_bf16.h>
#include <cstdint>

// Modulated deformable conv: deformable-im2col + tf32 mma.sync GEMM.
// R13: BM=128/NT=512 (halves weight L2 traffic), B-fill pipelined one full
// step ahead (wait_group 1), gather register-prefetched one step ahead.
//   M = 25088 px, N = 256 cout, K = 2304. CTA: 128 px x 256 cout, TK=32.

#define CIN   256
#define COUT  256
#define HH    56
#define WW    56
#define NB    8
#define KTAPS 9
#define HWSZ  (HH*WW)
#define MTOT  (NB*HWSZ)        // 25088 = 196*128

#define BM 128
#define BN 256
#define TK 32
#define NT 512
#define NSTEP (KTAPS*CIN/TK)   // 72
#define NCHUNK (CIN/TK)        // 8

#define AP 36                  // As row stride (floats), conflict-free frag loads

#define SM_A      0
#define ABUF      (BM*AP*4)            // 18432
#define SM_B      (2*ABUF)             // 36864
#define BBUF      (TK*BN*4)            // 32768 (u64-packed)
#define SM_TOTAL  (SM_B + 2*BBUF)      // 102400

typedef unsigned int u32;
typedef unsigned long long u64;

__device__ float g_xn[NB * HH * WW * CIN];          // NHWC fp32
__device__ u32   g_wB[KTAPS * NCHUNK * TK * COUT];  // tf32, u64-pair swizzled tiles

// ---------------- helpers ----------------
__device__ __forceinline__ u32 cvt_tf32(float f) {
    u32 r;
    asm("cvt.rna.tf32.f32 %0, %1;" : "=r"(r) : "f"(f));
    return r;
}
__device__ __forceinline__ void cp_async16(void* smem_dst, const void* gmem_src) {
    u32 sa = (u32)__cvta_generic_to_shared(smem_dst);
    asm volatile("cp.async.ca.shared.global [%0], [%1], 16;" :: "r"(sa), "l"(gmem_src));
}
__device__ __forceinline__ void cp_commit() { asm volatile("cp.async.commit_group;" ::: "memory"); }
__device__ __forceinline__ void cp_wait1()  { asm volatile("cp.async.wait_group 1;" ::: "memory"); }
__device__ __forceinline__ void cp_wait0()  { asm volatile("cp.async.wait_group 0;" ::: "memory"); }

__device__ __forceinline__ void mma_tf32(float* d, const u32* a, u32 b0, u32 b1) {
    asm volatile(
        "mma.sync.aligned.m16n8k8.row.col.f32.tf32.tf32.f32 "
        "{%0,%1,%2,%3}, {%4,%5,%6,%7}, {%8,%9}, {%0,%1,%2,%3};"
        : "+f"(d[0]), "+f"(d[1]), "+f"(d[2]), "+f"(d[3])
        : "r"(a[0]), "r"(a[1]), "r"(a[2]), "r"(a[3]), "r"(b0), "r"(b1));
}

// ---------------- prep kernels ----------------
__global__ void prep_w_kernel(const float* __restrict__ w) {
    int i = blockIdx.x * blockDim.x + threadIdx.x;
    if (i >= KTAPS * CIN * COUT) return;
    int k = i / (CIN * COUT);
    int r = i - k * (CIN * COUT);
    int o = r / CIN;
    int c = r - o * CIN;
    int chunk = c >> 5, cl = c & 31;
    int ks = cl >> 3, rem = cl & 7;
    int fc = rem & 3, half = rem >> 2;
    int i64 = o * 16 + ((ks * 4 + fc) ^ ((o & 3) << 2));
    g_wB[(k * NCHUNK + chunk) * (TK * COUT) + i64 * 2 + half] =
        cvt_tf32(w[(o * CIN + c) * KTAPS + k]);
}

__global__ void transpose_x_kernel(const float* __restrict__ x) {
    __shared__ float tile[32][33];
    int wT = blockIdx.x, cT = blockIdx.y, nh = blockIdx.z;
    int n = nh / HH, h = nh - n * HH;
    int tx = threadIdx.x, ty = threadIdx.y;
    #pragma unroll
    for (int i = 0; i < 4; ++i) {
        int c = cT * 32 + ty + i * 8;
        int w = wT * 32 + tx;
        if (w < WW)
            tile[ty + i * 8][tx] = x[((n * CIN + c) * HH + h) * WW + w];
    }
    __syncthreads();
    #pragma unroll
    for (int i = 0; i < 4; ++i) {
        int w = wT * 32 + ty + i * 8;
        int c = cT * 32 + tx;
        if (w < WW)
            g_xn[((n * HH + h) * WW + w) * CIN + c] = tile[tx][ty + i * 8];
    }
}

// ---------------- main kernel ----------------
__device__ __forceinline__ void calc_taps(int pg, int k,
                                          const float* __restrict__ offset,
                                          const float* __restrict__ mask,
                                          int* tb, float* tw) {
    int n = pg / HWSZ;
    int hw = pg - n * HWSZ;
    int h = hw / WW;
    int w = hw - h * WW;
    float dy = offset[((n * 18 + 2 * k    ) * HH + h) * WW + w];
    float dx = offset[((n * 18 + 2 * k + 1) * HH + h) * WW + w];
    float m  = mask  [((n * 9  + k        ) * HH + h) * WW + w];
    float py = dy + (float)(k / 3) + (float)(h - 1);
    float px = dx + (float)(k % 3) + (float)(w - 1);
    float y0f = floorf(py), x0f = floorf(px);
    float wy1 = py - y0f, wx1 = px - x0f;
    float wy0 = 1.0f - wy1, wx0 = 1.0f - wx1;
    int y0 = (int)y0f, x0 = (int)x0f;
    float w4[4] = { wy0 * wx0, wy0 * wx1, wy1 * wx0, wy1 * wx1 };
    #pragma unroll
    for (int t = 0; t < 4; ++t) {
        int yy = y0 + (t >> 1);
        int xx = x0 + (t & 1);
        bool valid = (yy >= 0) && (yy < HH) && (xx >= 0) && (xx < WW);
        int yc = min(max(yy, 0), HH - 1);
        int xc = min(max(xx, 0), WW - 1);
        tb[t] = ((n * HH + yc) * WW + xc) * CIN;
        tw[t] = valid ? w4[t] * m : 0.0f;
    }
}

__global__ __launch_bounds__(NT, 1) void mdcn_kernel(
    const float* __restrict__ offset,
    const float* __restrict__ mask,
    const float* __restrict__ bias,
    float* __restrict__ out)
{
    extern __shared__ char smem[];
    const int tid = threadIdx.x;
    const int wid = tid >> 5;
    const int lid = tid & 31;
    const int p0 = blockIdx.x * BM;

    const int wm = wid & 3;          // M warp (4)
    const int wn = wid >> 2;         // N warp (4)
    const int fr = lid >> 2;         // frag row group 0..7
    const int fc = lid & 3;          // frag col group 0..3

    const int pA = tid >> 2;         // gather pixel 0..127
    const int cq = tid & 3;          // gather quad

    int   tb[4];
    float tw[4];
    float4 rA[2][4];

    float acc[2][8][4];
    #pragma unroll
    for (int mt = 0; mt < 2; ++mt)
        #pragma unroll
        for (int nt = 0; nt < 8; ++nt)
            #pragma unroll
            for (int j = 0; j < 4; ++j) acc[mt][nt][j] = 0.0f;

    // ---- Prologue: taps + gather prefetch + B[0] issue ----
    calc_taps(p0 + pA, 0, offset, mask, tb, tw);
    #pragma unroll
    for (int half = 0; half < 2; ++half) {
        int c = cq * 4 + half * 16;
        #pragma unroll
        for (int t = 0; t < 4; ++t)
            rA[half][t] = *(const float4*)&g_xn[tb[t] + c];
    }
    {
        const char* src = (const char*)&g_wB[0];
        char* dstb = smem + SM_B;
        #pragma unroll
        for (int t = 0; t < 4; ++t) {
            int id = tid + t * NT;
            cp_async16(dstb + id * 16, src + id * 16);
        }
        cp_commit();
    }

    for (int step = 0; step < NSTEP; ++step) {
        const int buf = step & 1;

        // ---- combine prefetched corners -> tf32 -> As[buf] ----
        {
            char* abuf = smem + SM_A + buf * ABUF;
            #pragma unroll
            for (int half = 0; half < 2; ++half) {
                float4 v0 = rA[half][0], v1 = rA[half][1];
                float4 v2 = rA[half][2], v3 = rA[half][3];
                uint4 r;
                r.x = cvt_tf32(fmaf(tw[3], v3.x, fmaf(tw[2], v2.x, fmaf(tw[1], v1.x, tw[0] * v0.x))));
                r.y = cvt_tf32(fmaf(tw[3], v3.y, fmaf(tw[2], v2.y, fmaf(tw[1], v1.y, tw[0] * v0.y))));
                r.z = cvt_tf32(fmaf(tw[3], v3.z, fmaf(tw[2], v2.z, fmaf(tw[1], v1.z, tw[0] * v0.z))));
                r.w = cvt_tf32(fmaf(tw[3], v3.w, fmaf(tw[2], v2.w, fmaf(tw[1], v1.w, tw[0] * v0.w))));
                *(uint4*)(abuf + pA * (AP * 4) + cq * 16 + half * 64) = r;
            }
        }

        if (step + 1 < NSTEP) {
            // ---- issue B[step+1] into the other buffer ----
            {
                const int k2 = (step + 1) >> 3;
                const int chunk2 = (step + 1) & 7;
                const char* src = (const char*)&g_wB[(k2 * NCHUNK + chunk2) * (TK * COUT)];
                char* dstb = smem + SM_B + (buf ^ 1) * BBUF;
                #pragma unroll
                for (int t = 0; t < 4; ++t) {
                    int id = tid + t * NT;
                    cp_async16(dstb + id * 16, src + id * 16);
                }
                cp_commit();
            }
            // ---- prefetch gather for step+1 ----
            if (((step + 1) & 7) == 0)
                calc_taps(p0 + pA, (step + 1) >> 3, offset, mask, tb, tw);
            int c0n = ((step + 1) & 7) * TK;
            #pragma unroll
            for (int half = 0; half < 2; ++half) {
                int c = c0n + cq * 4 + half * 16;
                #pragma unroll
                for (int t = 0; t < 4; ++t)
                    rA[half][t] = *(const float4*)&g_xn[tb[t] + c];
            }
            cp_wait1();          // B[step] done (committed a full step ago)
        } else {
            cp_wait0();
        }
        __syncthreads();

        // ---- compute: 16 warps x (2 Mtiles x 8 Ntiles) m16n8k8 tf32 ----
        {
            const u32* As = (const u32*)(smem + SM_A + buf * ABUF);
            const u64* Bs64 = (const u64*)(smem + SM_B + buf * BBUF);
            const int cbase = (wn * 64 + fr) * 16;
            #pragma unroll
            for (int ks = 0; ks < 4; ++ks) {
                u32 a[2][4];
                #pragma unroll
                for (int mt = 0; mt < 2; ++mt) {
                    int px = wm * 32 + mt * 16 + fr;
                    int ci = ks * 8 + fc;
                    a[mt][0] = As[px * AP + ci];
                    a[mt][1] = As[(px + 8) * AP + ci];
                    a[mt][2] = As[px * AP + ci + 4];
                    a[mt][3] = As[(px + 8) * AP + ci + 4];
                }
                const int C = (ks * 4 + fc) ^ ((fr & 3) << 2);
                #pragma unroll
                for (int nt = 0; nt < 8; ++nt) {
                    u64 b = Bs64[cbase + nt * 128 + C];
                    u32 b0 = (u32)b, b1 = (u32)(b >> 32);
                    mma_tf32(acc[0][nt], a[0], b0, b1);
                    mma_tf32(acc[1][nt], a[1], b0, b1);
                }
            }
        }
        __syncthreads();
    }

    // ---- Epilogue (CTA may straddle images: per-pixel n) ----
    #pragma unroll
    for (int mt = 0; mt < 2; ++mt) {
        int pg = p0 + wm * 32 + mt * 16 + fr;      // first of the row pair
        int n0 = pg / HWSZ;
        int hw0 = pg - n0 * HWSZ;
        int pg8 = pg + 8;
        int n1 = pg8 / HWSZ;
        int hw1 = pg8 - n1 * HWSZ;
        #pragma unroll
        for (int nt = 0; nt < 8; ++nt) {
            int o0 = wn * 64 + nt * 8 + fc * 2;
            float b0 = __ldg(&bias[o0]);
            float b1 = __ldg(&bias[o0 + 1]);
            long baseA = (long)(n0 * COUT + o0) * HWSZ + hw0;
            long baseB = (long)(n1 * COUT + o0) * HWSZ + hw1;
            out[baseA]        = acc[mt][nt][0] + b0;
            out[baseA + HWSZ] = acc[mt][nt][1] + b1;
            out[baseB]        = acc[mt][nt][2] + b0;
            out[baseB + HWSZ] = acc[mt][nt][3] + b1;
        }
    }
}

extern "C" void kernel_launch(void* const* d_in, const int* in_sizes, int n_in,
                              void* d_out, int out_size) {
    const float* x      = (const float*)d_in[0];
    const float* offset = (const float*)d_in[1];
    const float* mask   = (const float*)d_in[2];
    const float* weight = (const float*)d_in[3];
    const float* bias   = (const float*)d_in[4];
    float* out = (float*)d_out;

    cudaFuncSetAttribute(mdcn_kernel, cudaFuncAttributeMaxDynamicSharedMemorySize, SM_TOTAL);

    prep_w_kernel<<<(KTAPS * CIN * COUT + 255) / 256, 256>>>(weight);
    {
        dim3 grid(2, 8, NB * HH);
        dim3 block(32, 8);
        transpose_x_kernel<<<grid, block>>>(x);
    }
    mdcn_kernel<<<MTOT / BM, NT, SM_TOTAL>>>(offset, mask, bias, out);
}

// round 14
// speedup vs baseline: 1.1515x; 1.1515x over previous
#include <cuda_runtime.h>
#include <cuda_bf16.h>
#include <cstdint>

// Modulated deformable conv: deformable-im2col + tf32 mma.sync GEMM.
// R14 = R12 (BM=64/NT=256, 2 CTAs/SM, gather register prefetch, u64-packed B)
//     + B-fill pipelined one FULL step ahead (cp.async.wait_group 1).
//   M = 25088 px, N = 256 cout, K = 2304. CTA: 64 px x 256 cout, TK=32.

#define CIN   256
#define COUT  256
#define HH    56
#define WW    56
#define NB    8
#define KTAPS 9
#define HWSZ  (HH*WW)
#define MTOT  (NB*HWSZ)        // 25088

#define BM 64
#define BN 256
#define TK 32
#define NT 256
#define NSTEP (KTAPS*CIN/TK)   // 72
#define NCHUNK (CIN/TK)        // 8

#define AP 36                  // As row stride (floats), conflict-free frag loads

#define SM_A      0
#define ABUF      (BM*AP*4)            // 9216
#define SM_B      (2*ABUF)             // 18432
#define BBUF      (TK*BN*4)            // 32768 (u64-packed)
#define SM_TOTAL  (SM_B + 2*BBUF)      // 83968

typedef unsigned int u32;
typedef unsigned long long u64;

__device__ float g_xn[NB * HH * WW * CIN];          // NHWC fp32
__device__ u32   g_wB[KTAPS * NCHUNK * TK * COUT];  // tf32, u64-pair swizzled tiles

// ---------------- helpers ----------------
__device__ __forceinline__ u32 cvt_tf32(float f) {
    u32 r;
    asm("cvt.rna.tf32.f32 %0, %1;" : "=r"(r) : "f"(f));
    return r;
}
__device__ __forceinline__ void cp_async16(void* smem_dst, const void* gmem_src) {
    u32 sa = (u32)__cvta_generic_to_shared(smem_dst);
    asm volatile("cp.async.ca.shared.global [%0], [%1], 16;" :: "r"(sa), "l"(gmem_src));
}
__device__ __forceinline__ void cp_commit() { asm volatile("cp.async.commit_group;" ::: "memory"); }
__device__ __forceinline__ void cp_wait1()  { asm volatile("cp.async.wait_group 1;" ::: "memory"); }
__device__ __forceinline__ void cp_wait0()  { asm volatile("cp.async.wait_group 0;" ::: "memory"); }

__device__ __forceinline__ void mma_tf32(float* d, const u32* a, u32 b0, u32 b1) {
    asm volatile(
        "mma.sync.aligned.m16n8k8.row.col.f32.tf32.tf32.f32 "
        "{%0,%1,%2,%3}, {%4,%5,%6,%7}, {%8,%9}, {%0,%1,%2,%3};"
        : "+f"(d[0]), "+f"(d[1]), "+f"(d[2]), "+f"(d[3])
        : "r"(a[0]), "r"(a[1]), "r"(a[2]), "r"(a[3]), "r"(b0), "r"(b1));
}

// ---------------- prep kernels ----------------
// weight [Cout][Cin][3][3] -> per-(tap,chunk) tile of u64 pairs:
//   u64 slot = col*16 + ((ks*4+fc) ^ ((col&3)<<2)); lo = row ks*8+fc, hi = +4
__global__ void prep_w_kernel(const float* __restrict__ w) {
    int i = blockIdx.x * blockDim.x + threadIdx.x;
    if (i >= KTAPS * CIN * COUT) return;
    int k = i / (CIN * COUT);
    int r = i - k * (CIN * COUT);
    int o = r / CIN;
    int c = r - o * CIN;
    int chunk = c >> 5, cl = c & 31;
    int ks = cl >> 3, rem = cl & 7;
    int fc = rem & 3, half = rem >> 2;
    int i64 = o * 16 + ((ks * 4 + fc) ^ ((o & 3) << 2));
    g_wB[(k * NCHUNK + chunk) * (TK * COUT) + i64 * 2 + half] =
        cvt_tf32(w[(o * CIN + c) * KTAPS + k]);
}

__global__ void transpose_x_kernel(const float* __restrict__ x) {
    __shared__ float tile[32][33];
    int wT = blockIdx.x, cT = blockIdx.y, nh = blockIdx.z;
    int n = nh / HH, h = nh - n * HH;
    int tx = threadIdx.x, ty = threadIdx.y;
    #pragma unroll
    for (int i = 0; i < 4; ++i) {
        int c = cT * 32 + ty + i * 8;
        int w = wT * 32 + tx;
        if (w < WW)
            tile[ty + i * 8][tx] = x[((n * CIN + c) * HH + h) * WW + w];
    }
    __syncthreads();
    #pragma unroll
    for (int i = 0; i < 4; ++i) {
        int w = wT * 32 + ty + i * 8;
        int c = cT * 32 + tx;
        if (w < WW)
            g_xn[((n * HH + h) * WW + w) * CIN + c] = tile[tx][ty + i * 8];
    }
}

// ---------------- main kernel ----------------
__device__ __forceinline__ void calc_taps(int pg, int k,
                                          const float* __restrict__ offset,
                                          const float* __restrict__ mask,
                                          int* tb, float* tw) {
    int n = pg / HWSZ;
    int hw = pg - n * HWSZ;
    int h = hw / WW;
    int w = hw - h * WW;
    float dy = offset[((n * 18 + 2 * k    ) * HH + h) * WW + w];
    float dx = offset[((n * 18 + 2 * k + 1) * HH + h) * WW + w];
    float m  = mask  [((n * 9  + k        ) * HH + h) * WW + w];
    float py = dy + (float)(k / 3) + (float)(h - 1);
    float px = dx + (float)(k % 3) + (float)(w - 1);
    float y0f = floorf(py), x0f = floorf(px);
    float wy1 = py - y0f, wx1 = px - x0f;
    float wy0 = 1.0f - wy1, wx0 = 1.0f - wx1;
    int y0 = (int)y0f, x0 = (int)x0f;
    float w4[4] = { wy0 * wx0, wy0 * wx1, wy1 * wx0, wy1 * wx1 };
    #pragma unroll
    for (int t = 0; t < 4; ++t) {
        int yy = y0 + (t >> 1);
        int xx = x0 + (t & 1);
        bool valid = (yy >= 0) && (yy < HH) && (xx >= 0) && (xx < WW);
        int yc = min(max(yy, 0), HH - 1);
        int xc = min(max(xx, 0), WW - 1);
        tb[t] = ((n * HH + yc) * WW + xc) * CIN;
        tw[t] = valid ? w4[t] * m : 0.0f;
    }
}

__global__ __launch_bounds__(NT, 2) void mdcn_kernel(
    const float* __restrict__ offset,
    const float* __restrict__ mask,
    const float* __restrict__ bias,
    float* __restrict__ out)
{
    extern __shared__ char smem[];
    const int tid = threadIdx.x;
    const int wid = tid >> 5;
    const int lid = tid & 31;
    const int p0 = blockIdx.x * BM;

    const int wm = wid & 1;          // M warp (2)
    const int wn = wid >> 1;         // N warp (4)
    const int fr = lid >> 2;         // frag row group 0..7
    const int fc = lid & 3;          // frag col group 0..3

    const int pA = tid >> 2;         // gather pixel 0..63
    const int cq = tid & 3;          // gather quad

    int   tb[4];
    float tw[4];
    float4 rA[2][4];

    float acc[2][8][4];
    #pragma unroll
    for (int mt = 0; mt < 2; ++mt)
        #pragma unroll
        for (int nt = 0; nt < 8; ++nt)
            #pragma unroll
            for (int j = 0; j < 4; ++j) acc[mt][nt][j] = 0.0f;

    // ---- Prologue: taps + gather prefetch + B[0] issue ----
    calc_taps(p0 + pA, 0, offset, mask, tb, tw);
    #pragma unroll
    for (int half = 0; half < 2; ++half) {
        int c = cq * 4 + half * 16;
        #pragma unroll
        for (int t = 0; t < 4; ++t)
            rA[half][t] = *(const float4*)&g_xn[tb[t] + c];
    }
    {
        const char* src = (const char*)&g_wB[0];
        char* dstb = smem + SM_B;
        #pragma unroll
        for (int t = 0; t < 8; ++t) {
            int id = tid + t * NT;
            cp_async16(dstb + id * 16, src + id * 16);
        }
        cp_commit();
    }

    for (int step = 0; step < NSTEP; ++step) {
        const int buf = step & 1;

        // ---- combine prefetched corners -> tf32 -> As[buf] ----
        {
            char* abuf = smem + SM_A + buf * ABUF;
            #pragma unroll
            for (int half = 0; half < 2; ++half) {
                float4 v0 = rA[half][0], v1 = rA[half][1];
                float4 v2 = rA[half][2], v3 = rA[half][3];
                uint4 r;
                r.x = cvt_tf32(fmaf(tw[3], v3.x, fmaf(tw[2], v2.x, fmaf(tw[1], v1.x, tw[0] * v0.x))));
                r.y = cvt_tf32(fmaf(tw[3], v3.y, fmaf(tw[2], v2.y, fmaf(tw[1], v1.y, tw[0] * v0.y))));
                r.z = cvt_tf32(fmaf(tw[3], v3.z, fmaf(tw[2], v2.z, fmaf(tw[1], v1.z, tw[0] * v0.z))));
                r.w = cvt_tf32(fmaf(tw[3], v3.w, fmaf(tw[2], v2.w, fmaf(tw[1], v1.w, tw[0] * v0.w))));
                *(uint4*)(abuf + pA * (AP * 4) + cq * 16 + half * 64) = r;
            }
        }

        if (step + 1 < NSTEP) {
            // ---- issue B[step+1] into the other buffer ----
            {
                const int k2 = (step + 1) >> 3;
                const int chunk2 = (step + 1) & 7;
                const char* src = (const char*)&g_wB[(k2 * NCHUNK + chunk2) * (TK * COUT)];
                char* dstb = smem + SM_B + (buf ^ 1) * BBUF;
                #pragma unroll
                for (int t = 0; t < 8; ++t) {
                    int id = tid + t * NT;
                    cp_async16(dstb + id * 16, src + id * 16);
                }
                cp_commit();
            }
            // ---- prefetch gather for step+1 (overlaps wait + MMA) ----
            if (((step + 1) & 7) == 0)
                calc_taps(p0 + pA, (step + 1) >> 3, offset, mask, tb, tw);
            int c0n = ((step + 1) & 7) * TK;
            #pragma unroll
            for (int half = 0; half < 2; ++half) {
                int c = c0n + cq * 4 + half * 16;
                #pragma unroll
                for (int t = 0; t < 4; ++t)
                    rA[half][t] = *(const float4*)&g_xn[tb[t] + c];
            }
            cp_wait1();          // B[step] complete (committed a full step ago)
        } else {
            cp_wait0();
        }
        __syncthreads();

        // ---- compute: 8 warps x (2 Mtiles x 8 Ntiles) m16n8k8 tf32 ----
        {
            const u32* As = (const u32*)(smem + SM_A + buf * ABUF);
            const u64* Bs64 = (const u64*)(smem + SM_B + buf * BBUF);
            const int cbase = (wn * 64 + fr) * 16;
            #pragma unroll
            for (int ks = 0; ks < 4; ++ks) {
                u32 a[2][4];
                #pragma unroll
                for (int mt = 0; mt < 2; ++mt) {
                    int px = wm * 32 + mt * 16 + fr;
                    int ci = ks * 8 + fc;
                    a[mt][0] = As[px * AP + ci];
                    a[mt][1] = As[(px + 8) * AP + ci];
                    a[mt][2] = As[px * AP + ci + 4];
                    a[mt][3] = As[(px + 8) * AP + ci + 4];
                }
                const int C = (ks * 4 + fc) ^ ((fr & 3) << 2);
                #pragma unroll
                for (int nt = 0; nt < 8; ++nt) {
                    u64 b = Bs64[cbase + nt * 128 + C];
                    u32 b0 = (u32)b, b1 = (u32)(b >> 32);
                    mma_tf32(acc[0][nt], a[0], b0, b1);
                    mma_tf32(acc[1][nt], a[1], b0, b1);
                }
            }
        }
        __syncthreads();
    }

    // ---- Epilogue ----
    const int n  = p0 / HWSZ;              // CTA never straddles images (3136%64==0)
    const int hw0 = p0 - n * HWSZ;
    #pragma unroll
    for (int nt = 0; nt < 8; ++nt) {
        int o0 = wn * 64 + nt * 8 + fc * 2;
        float b0 = __ldg(&bias[o0]);
        float b1 = __ldg(&bias[o0 + 1]);
        #pragma unroll
        for (int mt = 0; mt < 2; ++mt) {
            int hwA = hw0 + wm * 32 + mt * 16 + fr;
            long baseA = (long)(n * COUT + o0) * HWSZ + hwA;
            long baseB = baseA + 8;
            out[baseA]        = acc[mt][nt][0] + b0;
            out[baseA + HWSZ] = acc[mt][nt][1] + b1;
            out[baseB]        = acc[mt][nt][2] + b0;
            out[baseB + HWSZ] = acc[mt][nt][3] + b1;
        }
    }
}

extern "C" void kernel_launch(void* const* d_in, const int* in_sizes, int n_in,
                              void* d_out, int out_size) {
    const float* x      = (const float*)d_in[0];
    const float* offset = (const float*)d_in[1];
    const float* mask   = (const float*)d_in[2];
    const float* weight = (const float*)d_in[3];
    const float* bias   = (const float*)d_in[4];
    float* out = (float*)d_out;

    cudaFuncSetAttribute(mdcn_kernel, cudaFuncAttributeMaxDynamicSharedMemorySize, SM_TOTAL);

    prep_w_kernel<<<(KTAPS * CIN * COUT + 255) / 256, 256>>>(weight);
    {
        dim3 grid(2, 8, NB * HH);
        dim3 block(32, 8);
        transpose_x_kernel<<<grid, block>>>(x);
    }
    mdcn_kernel<<<MTOT / BM, NT, SM_TOTAL>>>(offset, mask, bias, out);
}